// round 6
// baseline (speedup 1.0000x reference)
#include <cuda_runtime.h>
#include <cstdint>

// Equivariant linear: segments (u,i) = (64,1),(32,3),(16,5); in==out dim 240.
// R5 compute shapes (balanced warp tiles, K-pair fma2 in seg1) +
// R3 orchestration (non-persistent CTAs, LDG/STS staging, one sync).

typedef unsigned long long u64;

__device__ __forceinline__ u64 fma2(u64 a, u64 b, u64 c) {
    u64 d;
    asm("fma.rn.f32x2 %0, %1, %2, %3;" : "=l"(d) : "l"(a), "l"(b), "l"(c));
    return d;
}
__device__ __forceinline__ u64 dup2(float x) {
    u64 d;
    asm("mov.b64 %0, {%1, %2};" : "=l"(d) : "f"(x), "f"(x));
    return d;
}
__device__ __forceinline__ float hsum2(u64 v) {
    float a, b;
    asm("mov.b64 {%0, %1}, %2;" : "=f"(a), "=f"(b) : "l"(v));
    return a + b;
}
__device__ __forceinline__ void unpack2(u64 v, float& a, float& b) {
    asm("mov.b64 {%0, %1}, %2;" : "=f"(a), "=f"(b) : "l"(v));
}

// smem layout (float offsets)
#define SW1_OFF 0       // 128 blocks x 36 floats
#define SW2_OFF 4608    // 1024 floats (row-major scaled copy; u64 = v-pairs)
#define SW3_OFF 5632    // 256 floats
#define SX_OFF  5888    // 64 rows x 248 floats
#define XSTRIDE 248
#define SMEM_FLOATS (5888 + 64 * 248)   // 21760 -> 87040 B

__global__ __launch_bounds__(256, 2) void eqlin_kernel(
    const float* __restrict__ x,
    const float* __restrict__ w,
    float* __restrict__ out,
    int n)
{
    extern __shared__ __align__(16) float sm[];
    float* sW1 = sm + SW1_OFF;
    float* sW2 = sm + SW2_OFF;
    float* sW3 = sm + SW3_OFF;
    float* sX  = sm + SX_OFF;

    const int tid = threadIdx.x;
    const long long base = (long long)blockIdx.x * 64;
    int rows = (int)(n - base);
    if (rows > 64) rows = 64;

    // ---- stage x tile: coalesced LDG.128 -> STS.128 into 248-stride rows ----
    #pragma unroll
    for (int m = 0; m < 15; m++) {
        int fq = tid + m * 256;                 // 0..3839 (64 rows x 60 quads)
        int r = fq / 60, q = fq - r * 60;
        long long gr = base + r;
        if (gr >= n) gr = n - 1;
        float4 v4 = *(const float4*)(x + gr * 240 + q * 4);
        *(float4*)(sX + r * XSTRIDE + q * 4) = v4;
    }

    // ---- build weight layouts (overlaps x staging in flight) ----
    // seg1: block b=(k4*2+vh)*4+lb, stride 36 floats (conflict-free)
    if (tid < 128) {
        int k4 = tid >> 3, vh = (tid >> 2) & 1, lb = tid & 3;
        float* blk = sW1 + tid * 36;
        #pragma unroll
        for (int j = 0; j < 2; j++)
            #pragma unroll
            for (int vv = 0; vv < 8; vv++) {
                int v = 32 * vh + 8 * lb + vv;
                int u0 = 4 * k4 + 2 * j;
                blk[(j * 8 + vv) * 2]     = w[u0 * 64 + v]       * 0.125f;
                blk[(j * 8 + vv) * 2 + 1] = w[(u0 + 1) * 64 + v] * 0.125f;
            }
    }
    #pragma unroll
    for (int i = tid; i < 1024; i += 256)
        sW2[i] = w[4096 + i] * 0.17677669529663687f;
    if (tid < 256)
        sW3[tid] = w[5120 + tid] * 0.25f;
    __syncthreads();

    const int warp = tid >> 5, lane = tid & 31;
    const int la = lane >> 2, lb = lane & 3;
    const int wy = warp >> 1, wx = warp & 1;

    // ================= Segment 1: 16r x 32v per warp, K-pair (no dups) =========
    {
        const int r0 = 16 * wy + 2 * la;
        const float* xb0 = sX + r0 * XSTRIDE;
        const float* xb1 = xb0 + XSTRIDE;
        u64 acc[2][8];
        #pragma unroll
        for (int rr = 0; rr < 2; rr++)
            #pragma unroll
            for (int vv = 0; vv < 8; vv++) acc[rr][vv] = 0ull;

        #pragma unroll 2
        for (int k4 = 0; k4 < 16; k4++) {
            const ulonglong2* W =
                (const ulonglong2*)(sW1 + (k4 * 8 + wx * 4 + lb) * 36);
            u64 wj0[8], wj1[8];
            #pragma unroll
            for (int q = 0; q < 4; q++) {
                ulonglong2 t0 = W[q];
                ulonglong2 t1 = W[q + 4];
                wj0[2 * q] = t0.x; wj0[2 * q + 1] = t0.y;
                wj1[2 * q] = t1.x; wj1[2 * q + 1] = t1.y;
            }
            ulonglong2 xq0 = *(const ulonglong2*)(xb0 + 4 * k4);
            ulonglong2 xq1 = *(const ulonglong2*)(xb1 + 4 * k4);
            #pragma unroll
            for (int vv = 0; vv < 8; vv++) {
                acc[0][vv] = fma2(xq0.y, wj1[vv], fma2(xq0.x, wj0[vv], acc[0][vv]));
                acc[1][vv] = fma2(xq1.y, wj1[vv], fma2(xq1.x, wj0[vv], acc[1][vv]));
            }
        }
        #pragma unroll
        for (int rr = 0; rr < 2; rr++) {
            if (r0 + rr >= rows) continue;
            float o[8];
            #pragma unroll
            for (int vv = 0; vv < 8; vv++) o[vv] = hsum2(acc[rr][vv]);
            float* p = out + (base + r0 + rr) * 240 + 32 * wx + 8 * lb;
            *(float4*)(p)     = make_float4(o[0], o[1], o[2], o[3]);
            *(float4*)(p + 4) = make_float4(o[4], o[5], o[6], o[7]);
        }
    }

    // ================= Segment 2: 16r x 16v per warp, v-pair =================
    {
        const int r0 = 16 * wy + 2 * la;
        const float* xb0 = sX + r0 * XSTRIDE + 64;
        const float* xb1 = xb0 + XSTRIDE;
        const int vp0 = 8 * wx + 2 * lb;
        u64 acc[2][2][3];
        #pragma unroll
        for (int rr = 0; rr < 2; rr++)
            #pragma unroll
            for (int vp = 0; vp < 2; vp++)
                #pragma unroll
                for (int i = 0; i < 3; i++) acc[rr][vp][i] = 0ull;

        #pragma unroll 2
        for (int k4 = 0; k4 < 8; k4++) {
            ulonglong2 Wu[4];
            #pragma unroll
            for (int u = 0; u < 4; u++)
                Wu[u] = *(const ulonglong2*)(sW2 + ((4 * k4 + u) * 16 + vp0) * 2);
            #pragma unroll
            for (int rr = 0; rr < 2; rr++) {
                const float* xb = rr ? xb1 : xb0;
                float4 xa = *(const float4*)(xb + 12 * k4);
                float4 xm = *(const float4*)(xb + 12 * k4 + 4);
                float4 xc = *(const float4*)(xb + 12 * k4 + 8);
                float xf[12] = {xa.x, xa.y, xa.z, xa.w, xm.x, xm.y,
                                xm.z, xm.w, xc.x, xc.y, xc.z, xc.w};
                #pragma unroll
                for (int u = 0; u < 4; u++)
                    #pragma unroll
                    for (int i = 0; i < 3; i++) {
                        u64 d = dup2(xf[3 * u + i]);
                        acc[rr][0][i] = fma2(d, Wu[u].x, acc[rr][0][i]);
                        acc[rr][1][i] = fma2(d, Wu[u].y, acc[rr][1][i]);
                    }
            }
        }
        #pragma unroll
        for (int rr = 0; rr < 2; rr++) {
            if (r0 + rr >= rows) continue;
            float f[12];
            #pragma unroll
            for (int vp = 0; vp < 2; vp++)
                #pragma unroll
                for (int i = 0; i < 3; i++) {
                    float lo, hi;
                    unpack2(acc[rr][vp][i], lo, hi);
                    f[6 * vp + i]     = lo;
                    f[6 * vp + 3 + i] = hi;
                }
            float* p = out + (base + r0 + rr) * 240 + 64 + 48 * wx + 12 * lb;
            *(float4*)(p)     = make_float4(f[0], f[1], f[2],  f[3]);
            *(float4*)(p + 4) = make_float4(f[4], f[5], f[6],  f[7]);
            *(float4*)(p + 8) = make_float4(f[8], f[9], f[10], f[11]);
        }
    }

    // ================= Segment 3: 8r x 16v per warp, v-pair =================
    {
        const int row = 8 * warp + la;
        const float* xb = sX + row * XSTRIDE + 160;
        const int vp0 = 2 * lb;
        u64 acc[2][5];
        #pragma unroll
        for (int vp = 0; vp < 2; vp++)
            #pragma unroll
            for (int i = 0; i < 5; i++) acc[vp][i] = 0ull;

        #pragma unroll
        for (int k4 = 0; k4 < 4; k4++) {
            ulonglong2 Wu[4];
            #pragma unroll
            for (int u = 0; u < 4; u++)
                Wu[u] = *(const ulonglong2*)(sW3 + ((4 * k4 + u) * 8 + vp0) * 2);
            float4 x0 = *(const float4*)(xb + 20 * k4);
            float4 x1 = *(const float4*)(xb + 20 * k4 + 4);
            float4 x2 = *(const float4*)(xb + 20 * k4 + 8);
            float4 x3 = *(const float4*)(xb + 20 * k4 + 12);
            float4 x4 = *(const float4*)(xb + 20 * k4 + 16);
            float xf[20] = {x0.x, x0.y, x0.z, x0.w, x1.x, x1.y, x1.z, x1.w,
                            x2.x, x2.y, x2.z, x2.w, x3.x, x3.y, x3.z, x3.w,
                            x4.x, x4.y, x4.z, x4.w};
            #pragma unroll
            for (int u = 0; u < 4; u++)
                #pragma unroll
                for (int i = 0; i < 5; i++) {
                    u64 d = dup2(xf[5 * u + i]);
                    acc[0][i] = fma2(d, Wu[u].x, acc[0][i]);
                    acc[1][i] = fma2(d, Wu[u].y, acc[1][i]);
                }
        }
        if (row < rows) {
            float f[20];
            #pragma unroll
            for (int vp = 0; vp < 2; vp++)
                #pragma unroll
                for (int i = 0; i < 5; i++) {
                    float lo, hi;
                    unpack2(acc[vp][i], lo, hi);
                    f[5 * (2 * vp) + i]     = lo;
                    f[5 * (2 * vp + 1) + i] = hi;
                }
            float* p = out + (base + row) * 240 + 160 + 20 * lb;
            *(float4*)(p)      = make_float4(f[0],  f[1],  f[2],  f[3]);
            *(float4*)(p + 4)  = make_float4(f[4],  f[5],  f[6],  f[7]);
            *(float4*)(p + 8)  = make_float4(f[8],  f[9],  f[10], f[11]);
            *(float4*)(p + 12) = make_float4(f[12], f[13], f[14], f[15]);
            *(float4*)(p + 16) = make_float4(f[16], f[17], f[18], f[19]);
        }
    }
}

extern "C" void kernel_launch(void* const* d_in, const int* in_sizes, int n_in,
                              void* d_out, int out_size) {
    const float* x = (const float*)d_in[0];
    const float* w = (const float*)d_in[1];
    float* out = (float*)d_out;
    const int n = in_sizes[0] / 240;            // 200000
    const int blocks = (n + 63) / 64;           // 3125 (exact)
    const int smem_bytes = SMEM_FLOATS * 4;     // 87040

    static bool attr_set = false;
    if (!attr_set) {
        cudaFuncSetAttribute(eqlin_kernel,
                             cudaFuncAttributeMaxDynamicSharedMemorySize, smem_bytes);
        attr_set = true;
    }
    eqlin_kernel<<<blocks, 256, smem_bytes>>>(x, w, out, n);
}

// round 8
// speedup vs baseline: 1.0601x; 1.0601x over previous
#include <cuda_runtime.h>

// Equivariant linear: segments (u,i) = (64,1),(32,3),(16,5); in==out dim 240.
// Base = proven 96us kernel; seg2/seg3 re-mapped to wider v-tiles per lane,
// strictly scalarized. R7 fix: seg3 stores via float2 (16B-misaligned offsets).

typedef unsigned long long u64;

__device__ __forceinline__ u64 fma2(u64 a, u64 b, u64 c) {
    u64 d;
    asm("fma.rn.f32x2 %0, %1, %2, %3;" : "=l"(d) : "l"(a), "l"(b), "l"(c));
    return d;
}
__device__ __forceinline__ u64 dup2(float x) {
    u64 d;
    asm("mov.b64 %0, {%1, %2};" : "=l"(d) : "f"(x), "f"(x));
    return d;
}
__device__ __forceinline__ void unpack2(u64 v, float& a, float& b) {
    asm("mov.b64 {%0, %1}, %2;" : "=f"(a), "=f"(b) : "l"(v));
}

#define ROW_PAD 244   // 244 mod 32 = 20 -> adjacent rows hit distinct banks

__global__ __launch_bounds__(256, 4) void eqlin_kernel(
    const float* __restrict__ x,
    const float* __restrict__ w,
    float* __restrict__ out,
    int n)
{
    extern __shared__ __align__(16) float smem[];
    float* sw = smem;                                   // 5376 floats (pre-scaled w)
    float (*sx)[ROW_PAD] = (float (*)[ROW_PAD])(smem + 5376);  // 32 x 244

    const int tid = threadIdx.x;

    // ---- stage weights, pre-scaled: seg1 *1/8, seg2 *1/sqrt(32), seg3 *1/4
    #pragma unroll
    for (int k = 0; k < 21; k++) {                      // 21*256 = 5376
        int idx = tid + k * 256;
        float s = (idx < 4096) ? 0.125f
                 : (idx < 5120) ? 0.17677669529663687f
                                : 0.25f;
        sw[idx] = w[idx] * s;
    }

    // ---- stage x tile, fully coalesced: 32 rows * 60 float4 = 1920 loads
    const long long rowbase = (long long)blockIdx.x * 32;
    #pragma unroll
    for (int k = 0; k < 8; k++) {
        int t = tid + k * 256;
        if (t < 1920) {
            int row = t / 60, c4 = t % 60;
            long long gr = rowbase + row;
            if (gr >= n) gr = n - 1;
            float4 v = *(const float4*)(x + gr * 240 + c4 * 4);
            *(float4*)&sx[row][c4 * 4] = v;
        }
    }
    __syncthreads();

    const int ty = tid >> 4;        // 0..15 -> 2 rows each (seg1)
    const int tx = tid & 15;        // seg1 v-slice
    const int r0 = ty * 2, r1 = r0 + 1;
    const long long g0 = rowbase + r0, g1 = rowbase + r1;
    const bool p0 = g0 < n, p1 = g1 < n;
    float* o0 = out + g0 * 240;
    float* o1 = out + g1 * 240;

    // ------------------------------------------------------------------
    // Segment 1 (UNCHANGED, proven): u=v=64, i=1, v = 4tx..4tx+3.
    // ------------------------------------------------------------------
    {
        const ulonglong2* w1p = (const ulonglong2*)sw;  // (u*64+4tx)/4 = u*16+tx
        u64 a0l = 0, a0h = 0, a1l = 0, a1h = 0;
        #pragma unroll 4
        for (int k = 0; k < 16; k++) {
            float4 xa = *(const float4*)&sx[r0][4 * k];
            float4 xb = *(const float4*)&sx[r1][4 * k];
            #pragma unroll
            for (int uu = 0; uu < 4; uu++) {
                ulonglong2 wp = w1p[(4 * k + uu) * 16 + tx];
                float s0 = (uu == 0) ? xa.x : (uu == 1) ? xa.y : (uu == 2) ? xa.z : xa.w;
                float s1 = (uu == 0) ? xb.x : (uu == 1) ? xb.y : (uu == 2) ? xb.z : xb.w;
                u64 d0 = dup2(s0), d1 = dup2(s1);
                a0l = fma2(d0, wp.x, a0l);  a0h = fma2(d0, wp.y, a0h);
                a1l = fma2(d1, wp.x, a1l);  a1h = fma2(d1, wp.y, a1h);
            }
        }
        if (p0) { float4 o; unpack2(a0l, o.x, o.y); unpack2(a0h, o.z, o.w);
                  *(float4*)(o0 + 4 * tx) = o; }
        if (p1) { float4 o; unpack2(a1l, o.x, o.y); unpack2(a1h, o.z, o.w);
                  *(float4*)(o1 + 4 * tx) = o; }
    }

    // ---- lane remap for seg2/seg3: 4 rows x 8 v-groups per warp ----
    const int warp = tid >> 5, lane = tid & 31;
    const int rq = lane >> 3;          // 0..3 : row within warp's 4 rows
    const int lv = lane & 7;           // 0..7 : v-group
    const int row32 = 4 * warp + rq;   // 0..31
    const long long grow = rowbase + row32;
    const bool prow = grow < n;
    const float* xr = &sx[row32][0];
    float* orow = out + grow * 240;

    // ------------------------------------------------------------------
    // Segment 2: u=v=32, i=3. Lane: 1 row x 4 v (v = 4lv..4lv+3).
    // w as ulonglong2 = ((w[u][4lv],w[u][4lv+1]),(w[u][4lv+2],w[u][4lv+3])).
    // ------------------------------------------------------------------
    {
        const ulonglong2* w2q = (const ulonglong2*)(sw + 4096);  // idx u*8+lv
        u64 aA0 = 0, aA1 = 0, aA2 = 0, aB0 = 0, aB1 = 0, aB2 = 0;

        #pragma unroll 2
        for (int k4 = 0; k4 < 8; k4++) {               // u = 4k4..4k4+3
            float4 q0 = *(const float4*)(xr + 64 + 12 * k4);
            float4 q1 = *(const float4*)(xr + 64 + 12 * k4 + 4);
            float4 q2 = *(const float4*)(xr + 64 + 12 * k4 + 8);
            ulonglong2 wu0 = w2q[(4 * k4 + 0) * 8 + lv];
            ulonglong2 wu1 = w2q[(4 * k4 + 1) * 8 + lv];
            ulonglong2 wu2 = w2q[(4 * k4 + 2) * 8 + lv];
            ulonglong2 wu3 = w2q[(4 * k4 + 3) * 8 + lv];
            u64 d;
            // u0: x = q0.x,q0.y,q0.z
            d = dup2(q0.x); aA0 = fma2(d, wu0.x, aA0); aB0 = fma2(d, wu0.y, aB0);
            d = dup2(q0.y); aA1 = fma2(d, wu0.x, aA1); aB1 = fma2(d, wu0.y, aB1);
            d = dup2(q0.z); aA2 = fma2(d, wu0.x, aA2); aB2 = fma2(d, wu0.y, aB2);
            // u1: q0.w, q1.x, q1.y
            d = dup2(q0.w); aA0 = fma2(d, wu1.x, aA0); aB0 = fma2(d, wu1.y, aB0);
            d = dup2(q1.x); aA1 = fma2(d, wu1.x, aA1); aB1 = fma2(d, wu1.y, aB1);
            d = dup2(q1.y); aA2 = fma2(d, wu1.x, aA2); aB2 = fma2(d, wu1.y, aB2);
            // u2: q1.z, q1.w, q2.x
            d = dup2(q1.z); aA0 = fma2(d, wu2.x, aA0); aB0 = fma2(d, wu2.y, aB0);
            d = dup2(q1.w); aA1 = fma2(d, wu2.x, aA1); aB1 = fma2(d, wu2.y, aB1);
            d = dup2(q2.x); aA2 = fma2(d, wu2.x, aA2); aB2 = fma2(d, wu2.y, aB2);
            // u3: q2.y, q2.z, q2.w
            d = dup2(q2.y); aA0 = fma2(d, wu3.x, aA0); aB0 = fma2(d, wu3.y, aB0);
            d = dup2(q2.z); aA1 = fma2(d, wu3.x, aA1); aB1 = fma2(d, wu3.y, aB1);
            d = dup2(q2.w); aA2 = fma2(d, wu3.x, aA2); aB2 = fma2(d, wu3.y, aB2);
        }
        if (prow) {
            // cols 64+12lv..+11 (offset 64+12lv is 4-aligned: OK for float4)
            float a0l, a0h, a1l, a1h, a2l, a2h;
            float b0l, b0h, b1l, b1h, b2l, b2h;
            unpack2(aA0, a0l, a0h); unpack2(aA1, a1l, a1h); unpack2(aA2, a2l, a2h);
            unpack2(aB0, b0l, b0h); unpack2(aB1, b1l, b1h); unpack2(aB2, b2l, b2h);
            float* p = orow + 64 + 12 * lv;
            *(float4*)(p)     = make_float4(a0l, a1l, a2l, a0h);
            *(float4*)(p + 4) = make_float4(a1h, a2h, b0l, b1l);
            *(float4*)(p + 8) = make_float4(b2l, b0h, b1h, b2h);
        }
    }

    // ------------------------------------------------------------------
    // Segment 3: u=v=16, i=5. Lane: 1 row x 2 v (v = 2lv, 2lv+1).
    // w u64 pair = (w[u][2lv], w[u][2lv+1]).
    // ------------------------------------------------------------------
    {
        const u64* w3q = (const u64*)(sw + 5120);      // idx u*8+lv
        u64 c0 = 0, c1 = 0, c2 = 0, c3 = 0, c4 = 0;

        #pragma unroll 2
        for (int k4 = 0; k4 < 4; k4++) {               // u = 4k4..4k4+3
            float4 q0 = *(const float4*)(xr + 160 + 20 * k4);
            float4 q1 = *(const float4*)(xr + 160 + 20 * k4 + 4);
            float4 q2 = *(const float4*)(xr + 160 + 20 * k4 + 8);
            float4 q3 = *(const float4*)(xr + 160 + 20 * k4 + 12);
            float4 q4 = *(const float4*)(xr + 160 + 20 * k4 + 16);
            u64 wu0 = w3q[(4 * k4 + 0) * 8 + lv];
            u64 wu1 = w3q[(4 * k4 + 1) * 8 + lv];
            u64 wu2 = w3q[(4 * k4 + 2) * 8 + lv];
            u64 wu3 = w3q[(4 * k4 + 3) * 8 + lv];
            // u0: q0.xyzw, q1.x
            c0 = fma2(dup2(q0.x), wu0, c0);
            c1 = fma2(dup2(q0.y), wu0, c1);
            c2 = fma2(dup2(q0.z), wu0, c2);
            c3 = fma2(dup2(q0.w), wu0, c3);
            c4 = fma2(dup2(q1.x), wu0, c4);
            // u1: q1.yzw, q2.xy
            c0 = fma2(dup2(q1.y), wu1, c0);
            c1 = fma2(dup2(q1.z), wu1, c1);
            c2 = fma2(dup2(q1.w), wu1, c2);
            c3 = fma2(dup2(q2.x), wu1, c3);
            c4 = fma2(dup2(q2.y), wu1, c4);
            // u2: q2.zw, q3.xyz
            c0 = fma2(dup2(q2.z), wu2, c0);
            c1 = fma2(dup2(q2.w), wu2, c1);
            c2 = fma2(dup2(q3.x), wu2, c2);
            c3 = fma2(dup2(q3.y), wu2, c3);
            c4 = fma2(dup2(q3.z), wu2, c4);
            // u3: q3.w, q4.xyzw
            c0 = fma2(dup2(q3.w), wu3, c0);
            c1 = fma2(dup2(q4.x), wu3, c1);
            c2 = fma2(dup2(q4.y), wu3, c2);
            c3 = fma2(dup2(q4.z), wu3, c3);
            c4 = fma2(dup2(q4.w), wu3, c4);
        }
        if (prow) {
            // cols 160+10lv..+9: offset is only 2-aligned for odd lv ->
            // write as five float2 (STG.64 legal at 8B alignment).
            float f0l, f0h, f1l, f1h, f2l, f2h, f3l, f3h, f4l, f4h;
            unpack2(c0, f0l, f0h); unpack2(c1, f1l, f1h); unpack2(c2, f2l, f2h);
            unpack2(c3, f3l, f3h); unpack2(c4, f4l, f4h);
            float* p = orow + 160 + 10 * lv;
            *(float2*)(p)     = make_float2(f0l, f1l);
            *(float2*)(p + 2) = make_float2(f2l, f3l);
            *(float2*)(p + 4) = make_float2(f4l, f0h);
            *(float2*)(p + 6) = make_float2(f1h, f2h);
            *(float2*)(p + 8) = make_float2(f3h, f4h);
        }
    }
}

extern "C" void kernel_launch(void* const* d_in, const int* in_sizes, int n_in,
                              void* d_out, int out_size) {
    const float* x = (const float*)d_in[0];
    const float* w = (const float*)d_in[1];
    float* out = (float*)d_out;
    const int n = in_sizes[0] / 240;              // 200000
    const int blocks = (n + 31) / 32;             // 6250 (exact)
    const int smem_bytes = (5376 + 32 * ROW_PAD) * 4;   // 52736
    static bool attr_set = false;
    if (!attr_set) {
        cudaFuncSetAttribute(eqlin_kernel,
                             cudaFuncAttributeMaxDynamicSharedMemorySize, smem_bytes);
        attr_set = true;
    }
    eqlin_kernel<<<blocks, 256, smem_bytes>>>(x, w, out, n);
}

// round 9
// speedup vs baseline: 1.0977x; 1.0355x over previous
#include <cuda_runtime.h>

// Equivariant linear: segments (u,i) = (64,1),(32,3),(16,5); in==out dim 240.
// R8 kernel with launch_bounds(256,2): lifts the 64-reg cap that caused
// local-memory spills (the real reason R8's L1 traffic exceeded R3's).

typedef unsigned long long u64;

__device__ __forceinline__ u64 fma2(u64 a, u64 b, u64 c) {
    u64 d;
    asm("fma.rn.f32x2 %0, %1, %2, %3;" : "=l"(d) : "l"(a), "l"(b), "l"(c));
    return d;
}
__device__ __forceinline__ u64 dup2(float x) {
    u64 d;
    asm("mov.b64 %0, {%1, %2};" : "=l"(d) : "f"(x), "f"(x));
    return d;
}
__device__ __forceinline__ void unpack2(u64 v, float& a, float& b) {
    asm("mov.b64 {%0, %1}, %2;" : "=f"(a), "=f"(b) : "l"(v));
}

#define ROW_PAD 244   // 244 mod 32 = 20 -> adjacent rows hit distinct banks

__global__ __launch_bounds__(256, 2) void eqlin_kernel(
    const float* __restrict__ x,
    const float* __restrict__ w,
    float* __restrict__ out,
    int n)
{
    extern __shared__ __align__(16) float smem[];
    float* sw = smem;                                   // 5376 floats (pre-scaled w)
    float (*sx)[ROW_PAD] = (float (*)[ROW_PAD])(smem + 5376);  // 32 x 244

    const int tid = threadIdx.x;

    // ---- stage weights, pre-scaled: seg1 *1/8, seg2 *1/sqrt(32), seg3 *1/4
    #pragma unroll
    for (int k = 0; k < 21; k++) {                      // 21*256 = 5376
        int idx = tid + k * 256;
        float s = (idx < 4096) ? 0.125f
                 : (idx < 5120) ? 0.17677669529663687f
                                : 0.25f;
        sw[idx] = w[idx] * s;
    }

    // ---- stage x tile, fully coalesced: 32 rows * 60 float4 = 1920 loads
    const long long rowbase = (long long)blockIdx.x * 32;
    #pragma unroll
    for (int k = 0; k < 8; k++) {
        int t = tid + k * 256;
        if (t < 1920) {
            int row = t / 60, c4 = t % 60;
            long long gr = rowbase + row;
            if (gr >= n) gr = n - 1;
            float4 v = *(const float4*)(x + gr * 240 + c4 * 4);
            *(float4*)&sx[row][c4 * 4] = v;
        }
    }
    __syncthreads();

    const int ty = tid >> 4;        // 0..15 -> 2 rows each (seg1)
    const int tx = tid & 15;        // seg1 v-slice
    const int r0 = ty * 2, r1 = r0 + 1;
    const long long g0 = rowbase + r0, g1 = rowbase + r1;
    const bool p0 = g0 < n, p1 = g1 < n;
    float* o0 = out + g0 * 240;
    float* o1 = out + g1 * 240;

    // ------------------------------------------------------------------
    // Segment 1: u=v=64, i=1, v = 4tx..4tx+3.
    // ------------------------------------------------------------------
    {
        const ulonglong2* w1p = (const ulonglong2*)sw;  // (u*64+4tx)/4 = u*16+tx
        u64 a0l = 0, a0h = 0, a1l = 0, a1h = 0;
        #pragma unroll 4
        for (int k = 0; k < 16; k++) {
            float4 xa = *(const float4*)&sx[r0][4 * k];
            float4 xb = *(const float4*)&sx[r1][4 * k];
            #pragma unroll
            for (int uu = 0; uu < 4; uu++) {
                ulonglong2 wp = w1p[(4 * k + uu) * 16 + tx];
                float s0 = (uu == 0) ? xa.x : (uu == 1) ? xa.y : (uu == 2) ? xa.z : xa.w;
                float s1 = (uu == 0) ? xb.x : (uu == 1) ? xb.y : (uu == 2) ? xb.z : xb.w;
                u64 d0 = dup2(s0), d1 = dup2(s1);
                a0l = fma2(d0, wp.x, a0l);  a0h = fma2(d0, wp.y, a0h);
                a1l = fma2(d1, wp.x, a1l);  a1h = fma2(d1, wp.y, a1h);
            }
        }
        if (p0) { float4 o; unpack2(a0l, o.x, o.y); unpack2(a0h, o.z, o.w);
                  *(float4*)(o0 + 4 * tx) = o; }
        if (p1) { float4 o; unpack2(a1l, o.x, o.y); unpack2(a1h, o.z, o.w);
                  *(float4*)(o1 + 4 * tx) = o; }
    }

    // ---- lane remap for seg2/seg3: 4 rows x 8 v-groups per warp ----
    const int warp = tid >> 5, lane = tid & 31;
    const int rq = lane >> 3;          // 0..3 : row within warp's 4 rows
    const int lv = lane & 7;           // 0..7 : v-group
    const int row32 = 4 * warp + rq;   // 0..31
    const long long grow = rowbase + row32;
    const bool prow = grow < n;
    const float* xr = &sx[row32][0];
    float* orow = out + grow * 240;

    // ------------------------------------------------------------------
    // Segment 2: u=v=32, i=3. Lane: 1 row x 4 v (v = 4lv..4lv+3).
    // ------------------------------------------------------------------
    {
        const ulonglong2* w2q = (const ulonglong2*)(sw + 4096);  // idx u*8+lv
        u64 aA0 = 0, aA1 = 0, aA2 = 0, aB0 = 0, aB1 = 0, aB2 = 0;

        #pragma unroll 2
        for (int k4 = 0; k4 < 8; k4++) {               // u = 4k4..4k4+3
            float4 q0 = *(const float4*)(xr + 64 + 12 * k4);
            float4 q1 = *(const float4*)(xr + 64 + 12 * k4 + 4);
            float4 q2 = *(const float4*)(xr + 64 + 12 * k4 + 8);
            ulonglong2 wu0 = w2q[(4 * k4 + 0) * 8 + lv];
            ulonglong2 wu1 = w2q[(4 * k4 + 1) * 8 + lv];
            ulonglong2 wu2 = w2q[(4 * k4 + 2) * 8 + lv];
            ulonglong2 wu3 = w2q[(4 * k4 + 3) * 8 + lv];
            u64 d;
            d = dup2(q0.x); aA0 = fma2(d, wu0.x, aA0); aB0 = fma2(d, wu0.y, aB0);
            d = dup2(q0.y); aA1 = fma2(d, wu0.x, aA1); aB1 = fma2(d, wu0.y, aB1);
            d = dup2(q0.z); aA2 = fma2(d, wu0.x, aA2); aB2 = fma2(d, wu0.y, aB2);
            d = dup2(q0.w); aA0 = fma2(d, wu1.x, aA0); aB0 = fma2(d, wu1.y, aB0);
            d = dup2(q1.x); aA1 = fma2(d, wu1.x, aA1); aB1 = fma2(d, wu1.y, aB1);
            d = dup2(q1.y); aA2 = fma2(d, wu1.x, aA2); aB2 = fma2(d, wu1.y, aB2);
            d = dup2(q1.z); aA0 = fma2(d, wu2.x, aA0); aB0 = fma2(d, wu2.y, aB0);
            d = dup2(q1.w); aA1 = fma2(d, wu2.x, aA1); aB1 = fma2(d, wu2.y, aB1);
            d = dup2(q2.x); aA2 = fma2(d, wu2.x, aA2); aB2 = fma2(d, wu2.y, aB2);
            d = dup2(q2.y); aA0 = fma2(d, wu3.x, aA0); aB0 = fma2(d, wu3.y, aB0);
            d = dup2(q2.z); aA1 = fma2(d, wu3.x, aA1); aB1 = fma2(d, wu3.y, aB1);
            d = dup2(q2.w); aA2 = fma2(d, wu3.x, aA2); aB2 = fma2(d, wu3.y, aB2);
        }
        if (prow) {
            float a0l, a0h, a1l, a1h, a2l, a2h;
            float b0l, b0h, b1l, b1h, b2l, b2h;
            unpack2(aA0, a0l, a0h); unpack2(aA1, a1l, a1h); unpack2(aA2, a2l, a2h);
            unpack2(aB0, b0l, b0h); unpack2(aB1, b1l, b1h); unpack2(aB2, b2l, b2h);
            float* p = orow + 64 + 12 * lv;
            *(float4*)(p)     = make_float4(a0l, a1l, a2l, a0h);
            *(float4*)(p + 4) = make_float4(a1h, a2h, b0l, b1l);
            *(float4*)(p + 8) = make_float4(b2l, b0h, b1h, b2h);
        }
    }

    // ------------------------------------------------------------------
    // Segment 3: u=v=16, i=5. Lane: 1 row x 2 v (v = 2lv, 2lv+1).
    // ------------------------------------------------------------------
    {
        const u64* w3q = (const u64*)(sw + 5120);      // idx u*8+lv
        u64 c0 = 0, c1 = 0, c2 = 0, c3 = 0, c4 = 0;

        #pragma unroll 2
        for (int k4 = 0; k4 < 4; k4++) {               // u = 4k4..4k4+3
            float4 q0 = *(const float4*)(xr + 160 + 20 * k4);
            float4 q1 = *(const float4*)(xr + 160 + 20 * k4 + 4);
            float4 q2 = *(const float4*)(xr + 160 + 20 * k4 + 8);
            float4 q3 = *(const float4*)(xr + 160 + 20 * k4 + 12);
            float4 q4 = *(const float4*)(xr + 160 + 20 * k4 + 16);
            u64 wu0 = w3q[(4 * k4 + 0) * 8 + lv];
            u64 wu1 = w3q[(4 * k4 + 1) * 8 + lv];
            u64 wu2 = w3q[(4 * k4 + 2) * 8 + lv];
            u64 wu3 = w3q[(4 * k4 + 3) * 8 + lv];
            c0 = fma2(dup2(q0.x), wu0, c0);
            c1 = fma2(dup2(q0.y), wu0, c1);
            c2 = fma2(dup2(q0.z), wu0, c2);
            c3 = fma2(dup2(q0.w), wu0, c3);
            c4 = fma2(dup2(q1.x), wu0, c4);
            c0 = fma2(dup2(q1.y), wu1, c0);
            c1 = fma2(dup2(q1.z), wu1, c1);
            c2 = fma2(dup2(q1.w), wu1, c2);
            c3 = fma2(dup2(q2.x), wu1, c3);
            c4 = fma2(dup2(q2.y), wu1, c4);
            c0 = fma2(dup2(q2.z), wu2, c0);
            c1 = fma2(dup2(q2.w), wu2, c1);
            c2 = fma2(dup2(q3.x), wu2, c2);
            c3 = fma2(dup2(q3.y), wu2, c3);
            c4 = fma2(dup2(q3.z), wu2, c4);
            c0 = fma2(dup2(q3.w), wu3, c0);
            c1 = fma2(dup2(q4.x), wu3, c1);
            c2 = fma2(dup2(q4.y), wu3, c2);
            c3 = fma2(dup2(q4.z), wu3, c3);
            c4 = fma2(dup2(q4.w), wu3, c4);
        }
        if (prow) {
            float f0l, f0h, f1l, f1h, f2l, f2h, f3l, f3h, f4l, f4h;
            unpack2(c0, f0l, f0h); unpack2(c1, f1l, f1h); unpack2(c2, f2l, f2h);
            unpack2(c3, f3l, f3h); unpack2(c4, f4l, f4h);
            float* p = orow + 160 + 10 * lv;
            *(float2*)(p)     = make_float2(f0l, f1l);
            *(float2*)(p + 2) = make_float2(f2l, f3l);
            *(float2*)(p + 4) = make_float2(f4l, f0h);
            *(float2*)(p + 6) = make_float2(f1h, f2h);
            *(float2*)(p + 8) = make_float2(f3h, f4h);
        }
    }
}

extern "C" void kernel_launch(void* const* d_in, const int* in_sizes, int n_in,
                              void* d_out, int out_size) {
    const float* x = (const float*)d_in[0];
    const float* w = (const float*)d_in[1];
    float* out = (float*)d_out;
    const int n = in_sizes[0] / 240;              // 200000
    const int blocks = (n + 31) / 32;             // 6250 (exact)
    const int smem_bytes = (5376 + 32 * ROW_PAD) * 4;   // 52736
    static bool attr_set = false;
    if (!attr_set) {
        cudaFuncSetAttribute(eqlin_kernel,
                             cudaFuncAttributeMaxDynamicSharedMemorySize, smem_bytes);
        attr_set = true;
    }
    eqlin_kernel<<<blocks, 256, smem_bytes>>>(x, w, out, n);
}

// round 10
// speedup vs baseline: 1.5200x; 1.3847x over previous
#include <cuda.h>
#include <cuda_runtime.h>
#include <cstdint>

// Equivariant linear: segments (u,i) = (64,1),(32,3),(16,5); in==out dim 240.
// R3 orchestration (64-row tile, TMA in/out, in-place smem output) with
// conflict-free sub-tile layout (cols 0-99 stride 100, cols 100-239 stride 140)
// + seg1/seg3 warp remaps for 1-wavefront shared loads.

typedef unsigned long long u64;

__device__ __forceinline__ u64 fma2(u64 a, u64 b, u64 c) {
    u64 d;
    asm("fma.rn.f32x2 %0, %1, %2, %3;" : "=l"(d) : "l"(a), "l"(b), "l"(c));
    return d;
}
__device__ __forceinline__ u64 dup2(float x) {
    u64 d;
    asm("mov.b64 %0, {%1, %2};" : "=l"(d) : "f"(x), "f"(x));
    return d;
}
__device__ __forceinline__ void unpack2(u64 v, float& a, float& b) {
    asm("mov.b64 {%0, %1}, %2;" : "=f"(a), "=f"(b) : "l"(v));
}
__device__ __forceinline__ uint32_t s2u(const void* p) {
    uint32_t a;
    asm("{ .reg .u64 t; cvta.to.shared.u64 t, %1; cvt.u32.u64 %0, t; }"
        : "=r"(a) : "l"(p));
    return a;
}
__device__ __forceinline__ void mbar_wait0(uint32_t mbar) {
    asm volatile(
        "{\n\t.reg .pred P;\n\t"
        "W%=:\n\t"
        "mbarrier.try_wait.parity.shared.b64 P, [%0], 0;\n\t"
        "@P bra.uni D%=;\n\t"
        "bra.uni W%=;\n\t"
        "D%=:\n\t}"
        :: "r"(mbar) : "memory");
}
__device__ __forceinline__ void tma_load2d(uint32_t dst, const CUtensorMap* m,
                                           int cx, int cy, uint32_t mbar) {
    asm volatile(
        "cp.async.bulk.tensor.2d.shared::cta.global.tile.mbarrier::complete_tx::bytes "
        "[%0], [%1, {%2, %3}], [%4];"
        :: "r"(dst), "l"(m), "r"(cx), "r"(cy), "r"(mbar) : "memory");
}
__device__ __forceinline__ void tma_store2d(const CUtensorMap* m, int cx, int cy,
                                            uint32_t src) {
    asm volatile(
        "cp.async.bulk.tensor.2d.global.shared::cta.tile.bulk_group "
        "[%0, {%1, %2}], [%3];"
        :: "l"(m), "r"(cx), "r"(cy), "r"(src) : "memory");
}

#define T0W 100
#define T1W 140
#define SX0_OFF 5376
#define SX1_OFF (SX0_OFF + 64 * T0W)      // 11776
#define MBAR_OFF (SX1_OFF + 64 * T1W)     // 20736
#define SMEM_BYTES ((MBAR_OFF + 4) * 4)   // 82960

__global__ __launch_bounds__(256, 2) void eqlin_kernel(
    const __grid_constant__ CUtensorMap mi0,
    const __grid_constant__ CUtensorMap mi1,
    const __grid_constant__ CUtensorMap mo0,
    const __grid_constant__ CUtensorMap mo1,
    const float* __restrict__ w)
{
    extern __shared__ __align__(128) float sm[];
    float* sw  = sm;
    float* sx0 = sm + SX0_OFF;
    float* sx1 = sm + SX1_OFF;
    const uint32_t mbar = s2u(sm + MBAR_OFF);

    const int tid = threadIdx.x;
    const int row0 = blockIdx.x * 64;

    if (tid == 0)
        asm volatile("mbarrier.init.shared.b64 [%0], 1;" :: "r"(mbar) : "memory");
    __syncthreads();
    if (tid == 0) {
        asm volatile("mbarrier.arrive.expect_tx.shared.b64 _, [%0], 61440;"
                     :: "r"(mbar) : "memory");
        tma_load2d(s2u(sx0), &mi0, 0,   row0, mbar);
        tma_load2d(s2u(sx1), &mi1, 100, row0, mbar);
    }

    // ---- stage weights (overlaps TMA), pre-scaled ----
    #pragma unroll
    for (int k = 0; k < 21; k++) {
        int idx = tid + k * 256;
        float s = (idx < 4096) ? 0.125f
                 : (idx < 5120) ? 0.17677669529663687f
                                : 0.25f;
        sw[idx] = w[idx] * s;
    }
    __syncthreads();
    mbar_wait0(mbar);

    const int warp = tid >> 5, lane = tid & 31;

    // ================= Segment 1: warp tile 16r x 32v ======================
    // warp: rg = warp>>1 (rows 16rg..), vh = warp&1 (v half)
    // lane: lv = lane&7 (v0 = 32vh+4lv), lr = lane>>3; rows 16rg + 4rr + lr
    {
        const int rg = warp >> 1, vh = warp & 1;
        const int lv = lane & 7, lr = lane >> 3;
        const int v0 = 32 * vh + 4 * lv;
        const ulonglong2* w1p = (const ulonglong2*)sw;
        const float* xb = sx0 + (16 * rg + lr) * T0W;

        u64 aA0 = 0, aB0 = 0, aA1 = 0, aB1 = 0;
        u64 aA2 = 0, aB2 = 0, aA3 = 0, aB3 = 0;

        #pragma unroll 4
        for (int k4 = 0; k4 < 16; k4++) {
            float4 x0 = *(const float4*)(xb + 0 * 4 * T0W + 4 * k4);
            float4 x1 = *(const float4*)(xb + 1 * 4 * T0W + 4 * k4);
            float4 x2 = *(const float4*)(xb + 2 * 4 * T0W + 4 * k4);
            float4 x3 = *(const float4*)(xb + 3 * 4 * T0W + 4 * k4);
            #pragma unroll
            for (int uu = 0; uu < 4; uu++) {
                ulonglong2 wp = w1p[(4 * k4 + uu) * 16 + 8 * vh + lv];
                float e0 = (uu == 0) ? x0.x : (uu == 1) ? x0.y : (uu == 2) ? x0.z : x0.w;
                float e1 = (uu == 0) ? x1.x : (uu == 1) ? x1.y : (uu == 2) ? x1.z : x1.w;
                float e2 = (uu == 0) ? x2.x : (uu == 1) ? x2.y : (uu == 2) ? x2.z : x2.w;
                float e3 = (uu == 0) ? x3.x : (uu == 1) ? x3.y : (uu == 2) ? x3.z : x3.w;
                u64 d0 = dup2(e0), d1 = dup2(e1), d2 = dup2(e2), d3 = dup2(e3);
                aA0 = fma2(d0, wp.x, aA0);  aB0 = fma2(d0, wp.y, aB0);
                aA1 = fma2(d1, wp.x, aA1);  aB1 = fma2(d1, wp.y, aB1);
                aA2 = fma2(d2, wp.x, aA2);  aB2 = fma2(d2, wp.y, aB2);
                aA3 = fma2(d3, wp.x, aA3);  aB3 = fma2(d3, wp.y, aB3);
            }
        }
        __syncthreads();   // all seg1 reads (cols 0-63) done everywhere
        float* pb = sx0 + (16 * rg + lr) * T0W + v0;
        {
            float4 o; unpack2(aA0, o.x, o.y); unpack2(aB0, o.z, o.w);
            *(float4*)(pb + 0 * 4 * T0W) = o;
        }
        {
            float4 o; unpack2(aA1, o.x, o.y); unpack2(aB1, o.z, o.w);
            *(float4*)(pb + 1 * 4 * T0W) = o;
        }
        {
            float4 o; unpack2(aA2, o.x, o.y); unpack2(aB2, o.z, o.w);
            *(float4*)(pb + 2 * 4 * T0W) = o;
        }
        {
            float4 o; unpack2(aA3, o.x, o.y); unpack2(aB3, o.z, o.w);
            *(float4*)(pb + 3 * 4 * T0W) = o;
        }
    }

    // ================= Segment 2: R3 shape, pointer-adjusted ================
    // ty = tid>>4 (rows ty+16s), tx = tid&15 (v-pair 2tx)
    {
        const int ty = tid >> 4, tx = tid & 15;
        const u64* w2p = (const u64*)(sw + 4096);
        u64 a2[4][3];
        #pragma unroll
        for (int s = 0; s < 4; s++)
            #pragma unroll
            for (int i = 0; i < 3; i++) a2[s][i] = 0ull;

        #pragma unroll
        for (int k4 = 0; k4 < 8; k4++) {        // k4 0-2: t0 (cols 64-99); 3-7: t1
            u64 wp0 = w2p[(4 * k4 + 0) * 16 + tx];
            u64 wp1 = w2p[(4 * k4 + 1) * 16 + tx];
            u64 wp2 = w2p[(4 * k4 + 2) * 16 + tx];
            u64 wp3 = w2p[(4 * k4 + 3) * 16 + tx];
            #pragma unroll
            for (int s = 0; s < 4; s++) {
                const int row = ty + 16 * s;
                const float* b = (k4 < 3) ? (sx0 + row * T0W + 64 + 12 * k4)
                                          : (sx1 + row * T1W + 12 * k4 - 36);
                float4 xb0 = *(const float4*)(b);
                float4 xb1 = *(const float4*)(b + 4);
                float4 xb2 = *(const float4*)(b + 8);
                a2[s][0] = fma2(dup2(xb0.x), wp0, a2[s][0]);
                a2[s][1] = fma2(dup2(xb0.y), wp0, a2[s][1]);
                a2[s][2] = fma2(dup2(xb0.z), wp0, a2[s][2]);
                a2[s][0] = fma2(dup2(xb0.w), wp1, a2[s][0]);
                a2[s][1] = fma2(dup2(xb1.x), wp1, a2[s][1]);
                a2[s][2] = fma2(dup2(xb1.y), wp1, a2[s][2]);
                a2[s][0] = fma2(dup2(xb1.z), wp2, a2[s][0]);
                a2[s][1] = fma2(dup2(xb1.w), wp2, a2[s][1]);
                a2[s][2] = fma2(dup2(xb2.x), wp2, a2[s][2]);
                a2[s][0] = fma2(dup2(xb2.y), wp3, a2[s][0]);
                a2[s][1] = fma2(dup2(xb2.z), wp3, a2[s][1]);
                a2[s][2] = fma2(dup2(xb2.w), wp3, a2[s][2]);
            }
        }
        __syncthreads();   // all seg2 reads (cols 64-159) done everywhere
        #pragma unroll
        for (int s = 0; s < 4; s++) {
            const int row = ty + 16 * s;
            float* p = (tx < 6) ? (sx0 + row * T0W + 64 + 6 * tx)
                                : (sx1 + row * T1W + 6 * tx - 36);
            float l0, h0, l1, h1, l2, h2;
            unpack2(a2[s][0], l0, h0);
            unpack2(a2[s][1], l1, h1);
            unpack2(a2[s][2], l2, h2);
            *(float2*)(p)     = make_float2(l0, l1);
            *(float2*)(p + 2) = make_float2(l2, h0);
            *(float2*)(p + 4) = make_float2(h1, h2);
        }
    }

    // ================= Segment 3: warp tile 8r x 16v, v-pairs ===============
    // lane: lv3 = lane&7 (v-pair 2lv3), lr3 = lane>>3; rows 8warp + 4rr + lr3
    {
        const int lv3 = lane & 7, lr3 = lane >> 3;
        const int rbase = 8 * warp + lr3;          // rows rbase, rbase+4
        const u64* w3q = (const u64*)(sw + 5120);  // pair idx u*8+lv3
        u64 cA0 = 0, cA1 = 0, cA2 = 0, cA3 = 0, cA4 = 0;
        u64 cB0 = 0, cB1 = 0, cB2 = 0, cB3 = 0, cB4 = 0;

        #pragma unroll
        for (int k4 = 0; k4 < 4; k4++) {
            const float* pa = sx1 + rbase * T1W + 60 + 20 * k4;
            const float* pb = pa + 4 * T1W;
            float4 qa0 = *(const float4*)(pa);
            float4 qa1 = *(const float4*)(pa + 4);
            float4 qa2 = *(const float4*)(pa + 8);
            float4 qa3 = *(const float4*)(pa + 12);
            float4 qa4 = *(const float4*)(pa + 16);
            float4 qb0 = *(const float4*)(pb);
            float4 qb1 = *(const float4*)(pb + 4);
            float4 qb2 = *(const float4*)(pb + 8);
            float4 qb3 = *(const float4*)(pb + 12);
            float4 qb4 = *(const float4*)(pb + 16);
            u64 wu0 = w3q[(4 * k4 + 0) * 8 + lv3];
            u64 wu1 = w3q[(4 * k4 + 1) * 8 + lv3];
            u64 wu2 = w3q[(4 * k4 + 2) * 8 + lv3];
            u64 wu3 = w3q[(4 * k4 + 3) * 8 + lv3];
            // u0: elems 0-4
            cA0 = fma2(dup2(qa0.x), wu0, cA0);  cB0 = fma2(dup2(qb0.x), wu0, cB0);
            cA1 = fma2(dup2(qa0.y), wu0, cA1);  cB1 = fma2(dup2(qb0.y), wu0, cB1);
            cA2 = fma2(dup2(qa0.z), wu0, cA2);  cB2 = fma2(dup2(qb0.z), wu0, cB2);
            cA3 = fma2(dup2(qa0.w), wu0, cA3);  cB3 = fma2(dup2(qb0.w), wu0, cB3);
            cA4 = fma2(dup2(qa1.x), wu0, cA4);  cB4 = fma2(dup2(qb1.x), wu0, cB4);
            // u1: elems 5-9
            cA0 = fma2(dup2(qa1.y), wu1, cA0);  cB0 = fma2(dup2(qb1.y), wu1, cB0);
            cA1 = fma2(dup2(qa1.z), wu1, cA1);  cB1 = fma2(dup2(qb1.z), wu1, cB1);
            cA2 = fma2(dup2(qa1.w), wu1, cA2);  cB2 = fma2(dup2(qb1.w), wu1, cB2);
            cA3 = fma2(dup2(qa2.x), wu1, cA3);  cB3 = fma2(dup2(qb2.x), wu1, cB3);
            cA4 = fma2(dup2(qa2.y), wu1, cA4);  cB4 = fma2(dup2(qb2.y), wu1, cB4);
            // u2: elems 10-14
            cA0 = fma2(dup2(qa2.z), wu2, cA0);  cB0 = fma2(dup2(qb2.z), wu2, cB0);
            cA1 = fma2(dup2(qa2.w), wu2, cA1);  cB1 = fma2(dup2(qb2.w), wu2, cB1);
            cA2 = fma2(dup2(qa3.x), wu2, cA2);  cB2 = fma2(dup2(qb3.x), wu2, cB2);
            cA3 = fma2(dup2(qa3.y), wu2, cA3);  cB3 = fma2(dup2(qb3.y), wu2, cB3);
            cA4 = fma2(dup2(qa3.z), wu2, cA4);  cB4 = fma2(dup2(qb3.z), wu2, cB4);
            // u3: elems 15-19
            cA0 = fma2(dup2(qa3.w), wu3, cA0);  cB0 = fma2(dup2(qb3.w), wu3, cB0);
            cA1 = fma2(dup2(qa4.x), wu3, cA1);  cB1 = fma2(dup2(qb4.x), wu3, cB1);
            cA2 = fma2(dup2(qa4.y), wu3, cA2);  cB2 = fma2(dup2(qb4.y), wu3, cB2);
            cA3 = fma2(dup2(qa4.z), wu3, cA3);  cB3 = fma2(dup2(qb4.z), wu3, cB3);
            cA4 = fma2(dup2(qa4.w), wu3, cA4);  cB4 = fma2(dup2(qb4.w), wu3, cB4);
        }
        __syncthreads();   // all seg3 reads (cols 160-239) done everywhere
        // v = 2lv3 gets lo of c0..c4 at +0..+4; v+1 gets hi at +5..+9
        float* pA = sx1 + rbase * T1W + 60 + 10 * lv3;
        float* pB = pA + 4 * T1W;
        float l0, h0, l1, h1, l2, h2, l3, h3, l4, h4;
        unpack2(cA0, l0, h0); unpack2(cA1, l1, h1); unpack2(cA2, l2, h2);
        unpack2(cA3, l3, h3); unpack2(cA4, l4, h4);
        *(float2*)(pA)     = make_float2(l0, l1);
        *(float2*)(pA + 2) = make_float2(l2, l3);
        *(float2*)(pA + 4) = make_float2(l4, h0);
        *(float2*)(pA + 6) = make_float2(h1, h2);
        *(float2*)(pA + 8) = make_float2(h3, h4);
        unpack2(cB0, l0, h0); unpack2(cB1, l1, h1); unpack2(cB2, l2, h2);
        unpack2(cB3, l3, h3); unpack2(cB4, l4, h4);
        *(float2*)(pB)     = make_float2(l0, l1);
        *(float2*)(pB + 2) = make_float2(l2, l3);
        *(float2*)(pB + 4) = make_float2(l4, h0);
        *(float2*)(pB + 6) = make_float2(h1, h2);
        *(float2*)(pB + 8) = make_float2(h3, h4);
    }

    __syncthreads();
    if (tid == 0) {
        asm volatile("fence.proxy.async;" ::: "memory");
        tma_store2d(&mo0, 0,   row0, s2u(sx0));
        tma_store2d(&mo1, 100, row0, s2u(sx1));
        asm volatile("cp.async.bulk.commit_group;" ::: "memory");
        asm volatile("cp.async.bulk.wait_group 0;" ::: "memory");
    }
}

// ===================== host side =====================

typedef CUresult (*TmapEncodeFn)(
    CUtensorMap*, CUtensorMapDataType, cuuint32_t, void*,
    const cuuint64_t*, const cuuint64_t*, const cuuint32_t*, const cuuint32_t*,
    CUtensorMapInterleave, CUtensorMapSwizzle, CUtensorMapL2promotion,
    CUtensorMapFloatOOBfill);

static void enc_map(TmapEncodeFn f, CUtensorMap* m, void* base, long long n,
                    uint32_t boxw) {
    cuuint64_t dims[2]    = {240, (cuuint64_t)n};
    cuuint64_t strides[1] = {240 * 4};
    cuuint32_t box[2]     = {boxw, 64};
    cuuint32_t es[2]      = {1, 1};
    f(m, CU_TENSOR_MAP_DATA_TYPE_FLOAT32, 2, base, dims, strides, box, es,
      CU_TENSOR_MAP_INTERLEAVE_NONE, CU_TENSOR_MAP_SWIZZLE_NONE,
      CU_TENSOR_MAP_L2_PROMOTION_L2_128B, CU_TENSOR_MAP_FLOAT_OOB_FILL_NONE);
}

extern "C" void kernel_launch(void* const* d_in, const int* in_sizes, int n_in,
                              void* d_out, int out_size) {
    void* x = d_in[0];
    const float* w = (const float*)d_in[1];
    const long long n = in_sizes[0] / 240;          // 200000
    const int blocks = (int)((n + 63) / 64);        // 3125

    void* fp = nullptr;
    cudaDriverEntryPointQueryResult qr;
#if CUDART_VERSION >= 12050
    cudaGetDriverEntryPointByVersion("cuTensorMapEncodeTiled", &fp, 12000,
                                     cudaEnableDefault, &qr);
#else
    cudaGetDriverEntryPoint("cuTensorMapEncodeTiled", &fp, cudaEnableDefault, &qr);
#endif
    TmapEncodeFn enc = (TmapEncodeFn)fp;

    CUtensorMap mi0, mi1, mo0, mo1;
    enc_map(enc, &mi0, x, n, 100);
    enc_map(enc, &mi1, x, n, 140);
    enc_map(enc, &mo0, d_out, n, 100);
    enc_map(enc, &mo1, d_out, n, 140);

    static bool attr_set = false;
    if (!attr_set) {
        cudaFuncSetAttribute(eqlin_kernel,
                             cudaFuncAttributeMaxDynamicSharedMemorySize, SMEM_BYTES);
        attr_set = true;
    }
    eqlin_kernel<<<blocks, 256, SMEM_BYTES>>>(mi0, mi1, mo0, mo1, w);
}